// round 13
// baseline (speedup 1.0000x reference)
#include <cuda_runtime.h>

// Fused 1-level DWT (analysis lowpass, stride 2, symmetric pad) + synthesis
// lowpass (transposed conv, dilation 2). 64 rows of length 524288.
//
//   cA[m]    = sum_i H[i] * sig_mir(2m + i - 8)
//   ya[2u]   = sum_r H[8-2r] * cA[u+r]
//   ya[2u+1] = sum_r H[9-2r] * cA[u+r]
// mirror: q<0 -> -1-q ; q>=L -> 2L-1-q.
//
// R11: R8 access structure (8 outputs/thread, 3 dense LDG.256 + 1 dense
// STG.256 => fully dense 1024B warp transactions, the measured L1 optimum),
// with 512-thread blocks for smoother SM fill (8192 blocks instead of 16384)
// and evict_first on the touch-once input stream. Runs at ~87% of HBM spec.

#define THREADS   512
#define PER_THR   8
#define TILE      (THREADS * PER_THR)   // 4096 outputs per block

__device__ __forceinline__ void ldg256_stream(const float* __restrict__ p, float v[8])
{
    asm volatile("ld.global.nc.L2::evict_first.v8.f32 {%0,%1,%2,%3,%4,%5,%6,%7}, [%8];"
                 : "=f"(v[0]), "=f"(v[1]), "=f"(v[2]), "=f"(v[3]),
                   "=f"(v[4]), "=f"(v[5]), "=f"(v[6]), "=f"(v[7])
                 : "l"(p));
}

__device__ __forceinline__ void stg256(float* p, const float v[8])
{
    asm volatile("st.global.v8.f32 [%0], {%1,%2,%3,%4,%5,%6,%7,%8};"
                 :: "l"(p),
                    "f"(v[0]), "f"(v[1]), "f"(v[2]), "f"(v[3]),
                    "f"(v[4]), "f"(v[5]), "f"(v[6]), "f"(v[7])
                 : "memory");
}

__global__ __launch_bounds__(THREADS)
void wavelet_v8w_kernel(const float* __restrict__ x,
                        float* __restrict__ y,
                        int L, int tilesPerRow)
{
    const int tile = blockIdx.x;
    const int row  = blockIdx.y;
    const long long rowbase = (long long)row * (long long)L;
    const float* xr = x + rowbase;

    const int t0 = tile * TILE + threadIdx.x * PER_THR;  // first output index

    float xv[24];  // sig[t0-8 .. t0+15]

    if (tile == 0 || tile == tilesPerRow - 1) {
        // boundary tiles (128 of 8192 blocks): scalar mirrored loads
        #pragma unroll
        for (int i = 0; i < 24; i++) {
            int q = t0 - 8 + i;
            if (q < 0)        q = -1 - q;
            else if (q >= L)  q = 2 * L - 1 - q;
            xv[i] = xr[q];
        }
    } else {
        // interior: 3 independent dense 256-bit loads (32B-aligned)
        ldg256_stream(xr + t0 - 8, xv + 0);
        ldg256_stream(xr + t0,     xv + 8);
        ldg256_stream(xr + t0 + 8, xv + 16);
    }

    constexpr float H[10] = {
        0.160102397974125f,     0.6038292697974729f,
        0.7243085284385744f,    0.13842814590110342f,
       -0.24229488706619015f,  -0.03224486958502952f,
        0.07757149384006515f,  -0.006241490213011705f,
       -0.012580751999015526f,  0.003335725285001549f
    };

    // stage 1: 8 approximation coefficients
    float cA[8];
    #pragma unroll
    for (int r = 0; r < 8; r++) {
        float a = 0.0f;
        #pragma unroll
        for (int i = 0; i < 10; i++) {
            a = fmaf(H[i], xv[2*r + i], a);
        }
        cA[r] = a;
    }

    // stage 2: 8 outputs (4 even/odd pairs)
    float o[8];
    #pragma unroll
    for (int s = 0; s < 4; s++) {
        float e = 0.0f, od = 0.0f;
        #pragma unroll
        for (int rp = 0; rp < 5; rp++) {
            e  = fmaf(H[8 - 2*rp], cA[s + rp], e);
            od = fmaf(H[9 - 2*rp], cA[s + rp], od);
        }
        o[2*s + 0] = e;
        o[2*s + 1] = od;
    }

    // one dense 256-bit store (32B-aligned)
    stg256(y + rowbase + t0, o);
}

extern "C" void kernel_launch(void* const* d_in, const int* in_sizes, int n_in,
                              void* d_out, int out_size)
{
    const float* x = (const float*)d_in[0];
    float* y = (float*)d_out;

    const int B = 64;
    const int total = in_sizes[0];          // 64 * 128 * 4096
    const int L = total / B;                // 524288
    const int tilesPerRow = L / TILE;       // 128

    dim3 grid(tilesPerRow, B);
    wavelet_v8w_kernel<<<grid, THREADS>>>(x, y, L, tilesPerRow);
}

// round 15
// speedup vs baseline: 1.0616x; 1.0616x over previous
#include <cuda_runtime.h>

// Fused 1-level DWT (analysis lowpass, stride 2, symmetric pad) + synthesis
// lowpass (transposed conv, dilation 2). 64 rows of length 524288.
//
//   cA[m]    = sum_i H[i] * sig_mir(2m + i - 8)
//   ya[2u]   = sum_r H[8-2r] * cA[u+r]
//   ya[2u+1] = sum_r H[9-2r] * cA[u+r]
// mirror: q<0 -> -1-q ; q>=L -> 2L-1-q.
//
// FINAL (R8 config): 8 outputs/thread, 3 dense LDG.256 + 1 dense STG.256 —
// every warp memory access is a fully dense 1024B transaction (100% L1 line
// efficiency, 32 wavefronts/256 outputs). No smem, no shuffles, no hints.
// Runs at ~6.95 TB/s effective = ~87% of HBM3e spec; DRAM-roofline-bound.

#define TILE      2048
#define THREADS   256
#define PER_THR   8

__device__ __forceinline__ void ldg256(const float* __restrict__ p, float v[8])
{
    asm volatile("ld.global.nc.v8.f32 {%0,%1,%2,%3,%4,%5,%6,%7}, [%8];"
                 : "=f"(v[0]), "=f"(v[1]), "=f"(v[2]), "=f"(v[3]),
                   "=f"(v[4]), "=f"(v[5]), "=f"(v[6]), "=f"(v[7])
                 : "l"(p));
}

__device__ __forceinline__ void stg256(float* p, const float v[8])
{
    asm volatile("st.global.v8.f32 [%0], {%1,%2,%3,%4,%5,%6,%7,%8};"
                 :: "l"(p),
                    "f"(v[0]), "f"(v[1]), "f"(v[2]), "f"(v[3]),
                    "f"(v[4]), "f"(v[5]), "f"(v[6]), "f"(v[7])
                 : "memory");
}

__global__ __launch_bounds__(THREADS)
void wavelet_v8_kernel(const float* __restrict__ x,
                       float* __restrict__ y,
                       int L, int tilesPerRow)
{
    const int tile = blockIdx.x;
    const int row  = blockIdx.y;
    const long long rowbase = (long long)row * (long long)L;
    const float* xr = x + rowbase;

    const int t0 = tile * TILE + threadIdx.x * PER_THR;  // first output index

    float xv[24];  // sig[t0-8 .. t0+15]

    if (tile == 0 || tile == tilesPerRow - 1) {
        // boundary tiles (128 of 16384 blocks): scalar mirrored loads
        #pragma unroll
        for (int i = 0; i < 24; i++) {
            int q = t0 - 8 + i;
            if (q < 0)        q = -1 - q;
            else if (q >= L)  q = 2 * L - 1 - q;
            xv[i] = xr[q];
        }
    } else {
        // interior: 3 independent dense 256-bit loads (32B-aligned)
        ldg256(xr + t0 - 8, xv + 0);
        ldg256(xr + t0,     xv + 8);
        ldg256(xr + t0 + 8, xv + 16);
    }

    constexpr float H[10] = {
        0.160102397974125f,     0.6038292697974729f,
        0.7243085284385744f,    0.13842814590110342f,
       -0.24229488706619015f,  -0.03224486958502952f,
        0.07757149384006515f,  -0.006241490213011705f,
       -0.012580751999015526f,  0.003335725285001549f
    };

    // stage 1: 8 approximation coefficients
    float cA[8];
    #pragma unroll
    for (int r = 0; r < 8; r++) {
        float a = 0.0f;
        #pragma unroll
        for (int i = 0; i < 10; i++) {
            a = fmaf(H[i], xv[2*r + i], a);
        }
        cA[r] = a;
    }

    // stage 2: 8 outputs (4 even/odd pairs)
    float o[8];
    #pragma unroll
    for (int s = 0; s < 4; s++) {
        float e = 0.0f, od = 0.0f;
        #pragma unroll
        for (int rp = 0; rp < 5; rp++) {
            e  = fmaf(H[8 - 2*rp], cA[s + rp], e);
            od = fmaf(H[9 - 2*rp], cA[s + rp], od);
        }
        o[2*s + 0] = e;
        o[2*s + 1] = od;
    }

    // one dense 256-bit store (32B-aligned)
    stg256(y + rowbase + t0, o);
}

extern "C" void kernel_launch(void* const* d_in, const int* in_sizes, int n_in,
                              void* d_out, int out_size)
{
    const float* x = (const float*)d_in[0];
    float* y = (float*)d_out;

    const int B = 64;
    const int total = in_sizes[0];          // 64 * 128 * 4096
    const int L = total / B;                // 524288
    const int tilesPerRow = L / TILE;       // 256

    dim3 grid(tilesPerRow, B);
    wavelet_v8_kernel<<<grid, THREADS>>>(x, y, L, tilesPerRow);
}